// round 8
// baseline (speedup 1.0000x reference)
#include <cuda_runtime.h>
#include <cuda_bf16.h>
#include <math.h>

#define A_TOT 147456      // 128*128*9 anchors
#define HW    16384
#define GW    128
#define CIN   512
#define KTOT  4608        // 512*9
#define KSPLIT 4
#define KCH   1152        // KTOT/KSPLIT
#define NCOL  1280        // original columns: 512 pos-bbox + 256 pos-score + 512 neg-score
#define NU2   1088        // max unique columns padded (513 + 4*128 -> 1025 -> 1088)
#define NBLK  576         // A_TOT/256
#define STEP  (2048.0f/127.0f)

__constant__ float d_whw[9] = {128.0f, 181.01933598375618f, 90.50966799187809f,
                               256.0f, 362.03867196751236f, 181.01933598375618f,
                               512.0f, 724.0773439350247f, 362.03867196751236f};
__constant__ float d_whh[9] = {128.0f, 90.50966799187809f, 181.01933598375618f,
                               256.0f, 181.01933598375618f, 362.03867196751236f,
                               512.0f, 362.03867196751236f, 724.0773439350247f};

// ---------------- static device scratch ----------------
__device__ float d_maxIou[A_TOT];
__device__ int   d_tgtIdx[A_TOT];
__device__ int   d_posIdx[128];
__device__ int   d_posValid[128];
__device__ int   d_negValid[256];
__device__ int   d_nPos;
__device__ int   d_Upad;              // padded unique-column count (multiple of 64)
__device__ int   d_colPos[NCOL];      // spatial position per ORIGINAL column (valid only)
__device__ int   d_colMeta[NCOL];     // weight row per original column (valid only)
__device__ int   d_uniqPos[NU2];      // spatial position per UNIQUE column
__device__ float d_Bg[KTOT * NU2];    // gathered patches [k][u]
__device__ float d_hp[KSPLIT * NU2 * CIN]; // GEMM partials [ks][u][m]
__device__ float d_val[NCOL];

// ---------------- packed fp32 FMA ----------------
__device__ __forceinline__ unsigned long long ffma2(unsigned long long a,
                                                    unsigned long long b,
                                                    unsigned long long c) {
    unsigned long long d;
    asm("fma.rn.f32x2 %0, %1, %2, %3;" : "=l"(d) : "l"(a), "l"(b), "l"(c));
    return d;
}

// ---------------- phase A: IoU matching ----------------
__global__ void iou_kernel(const float* __restrict__ target) {
    __shared__ float4 tg[64];
    int t = threadIdx.x;
    if (t < 64) tg[t] = ((const float4*)target)[t];
    __syncthreads();
    int a = blockIdx.x * 256 + t;
    int k = a % 9;
    int q = a / 9;
    int wq = q & 127;
    int hq = q >> 7;
    float x1 = hq * STEP;
    float y1 = wq * STEP;
    float x2 = x1 + d_whw[k];
    float y2 = y1 + d_whh[k];
    float areaA = (x2 - x1) * (y2 - y1);

    float best = -1.0f;
    int bi = 0;
    #pragma unroll 4
    for (int i = 0; i < 64; i++) {
        float4 b = tg[i];
        float lx = fmaxf(b.x, x1), ly = fmaxf(b.y, y1);
        float rx = fminf(b.z, x2), ry = fminf(b.w, y2);
        float iw = fmaxf(rx - lx, 0.0f), ih = fmaxf(ry - ly, 0.0f);
        float inter = iw * ih;
        float at = (b.z - b.x) * (b.w - b.y);
        float iou = inter / (at + areaA - inter);
        if (iou > best) { best = iou; bi = i; }   // first-max == jnp.argmax
    }
    d_maxIou[a] = best;
    d_tgtIdx[a] = bi;
}

// ---------------- fallback sort helper (1024 threads) ----------------
__device__ __forceinline__ void bitonic2048(unsigned long long* s) {
    int t = threadIdx.x;
    for (int k = 2; k <= 2048; k <<= 1) {
        for (int j = k >> 1; j > 0; j >>= 1) {
            __syncthreads();
            #pragma unroll
            for (int base = 0; base < 2048; base += 1024) {
                int i = base + t;
                int ixj = i ^ j;
                if (ixj > i) {
                    unsigned long long va = s[i], vb = s[ixj];
                    bool sw = ((i & k) == 0) ? (va < vb) : (va > vb);
                    if (sw) { s[i] = vb; s[ixj] = va; }
                }
            }
        }
    }
    __syncthreads();
}

// ---------------- phase B: ONE-kernel selection + column tables ----------------
__global__ void selection_kernel() {   // 1 block x 1024 threads
    __shared__ unsigned long long pKeys[2048];
    __shared__ int zIdx[256];
    __shared__ int wz[32], wp[32];
    __shared__ int zTot, pTot, zBase, pBase;
    int t = threadIdx.x, lane = t & 31, w = t >> 5;
    if (t == 0) { zTot = 0; pTot = 0; }
    __syncthreads();

    for (int it = 0; it < A_TOT / 1024; it++) {
        int a = it * 1024 + t;
        float best = d_maxIou[a];
        bool zf = (zTot < 256);                    // uniform (post-sync read)
        bool z = zf && (best < 0.3f) && ((1.0f - best) == 1.0f);  // exact ref tie-class
        bool p = (best > 0.7f);
        unsigned zb = __ballot_sync(0xFFFFFFFFu, z);
        unsigned pb = __ballot_sync(0xFFFFFFFFu, p);
        if (lane == 0) { wz[w] = __popc(zb); wp[w] = __popc(pb); }
        __syncthreads();
        if (w == 0) {
            int vz = wz[lane], vp = wp[lane];
            int sz = vz, sp = vp;
            #pragma unroll
            for (int o = 1; o < 32; o <<= 1) {
                int xz = __shfl_up_sync(0xFFFFFFFFu, sz, o);
                int xp = __shfl_up_sync(0xFFFFFFFFu, sp, o);
                if (lane >= o) { sz += xz; sp += xp; }
            }
            wz[lane] = sz - vz;                    // exclusive prefix
            wp[lane] = sp - vp;
            if (lane == 31) {
                zBase = zTot; pBase = pTot;
                zTot = zTot + sz; pTot = pTot + sp;
            }
        }
        __syncthreads();
        if (z) {
            int r = zBase + wz[w] + __popc(zb & ((1u << lane) - 1));
            if (r < 256) zIdx[r] = a;
        }
        if (p) {
            int r = pBase + wp[w] + __popc(pb & ((1u << lane) - 1));
            if (r < 2048)
                pKeys[r] = (((unsigned long long)__float_as_uint(best) << 32) |
                            (0xFFFFFFFFu - (unsigned)a));
        }
        __syncthreads();
    }

    int cnt = pTot;
    int npos = cnt < 128 ? cnt : 128;
    int K = 256 - npos;
    if (t == 0) {
        d_nPos = npos;
        int U = 513 + 4 * npos;
        d_Upad = (U + 63) & ~63;
    }
    if (cnt > 128) {
        // rare fallback: exact top-128 by (iou desc, index asc)
        int stored = cnt < 2048 ? cnt : 2048;
        for (int i = t; i < 2048; i += 1024)
            if (i >= stored) pKeys[i] = 0ULL;
        __syncthreads();
        bitonic2048(pKeys);
    }
    __syncthreads();
    if (t < 128) {
        int valid = (t < npos);
        d_posValid[t] = valid;
        if (valid) {
            int p = (int)(0xFFFFFFFFu - (unsigned)(pKeys[t] & 0xFFFFFFFFULL));
            d_posIdx[t] = p;
            int sb = (4 * p) & 16383;
            int ssc = (2 * p) & 16383;
            int cb = p >> 12;
            int cs = 36 + (p >> 13);
            #pragma unroll
            for (int e = 0; e < 4; e++) {
                d_colPos[4 * t + e] = sb + e;
                d_colMeta[4 * t + e] = cb;
            }
            #pragma unroll
            for (int e = 0; e < 2; e++) {
                d_colPos[512 + 2 * t + e] = ssc + e;
                d_colMeta[512 + 2 * t + e] = cs;
            }
        }
    }
    if (t < 256) {
        d_negValid[t] = (t < K);
        if (t < K) {
            int a = zIdx[t];
            int ss = (2 * a) & 16383;
            int cs = 36 + (a >> 13);
            d_colPos[768 + 2 * t] = ss;         d_colMeta[768 + 2 * t] = cs;
            d_colPos[768 + 2 * t + 1] = ss + 1; d_colMeta[768 + 2 * t + 1] = cs;
        }
    }
    __syncthreads();
    // unique-position table: u=0 shared by all invalid cols; u>=1 valid cols in order
    for (int u = t; u < NU2; u += 1024) {
        int pos = 0;
        if (u >= 1) {
            int v = u - 1;
            if (v < 4 * npos)              pos = d_colPos[v];
            else if (v < 6 * npos)         pos = d_colPos[512 + (v - 4 * npos)];
            else if (v < 6 * npos + 2 * K) pos = d_colPos[768 + (v - 6 * npos)];
        }
        d_uniqPos[u] = pos;
    }
}

// ---------------- gather 3x3 input patches: Bg[k][u] ----------------
__global__ void gather_kernel(const float* __restrict__ x) {
    int t = threadIdx.x;
    int n = blockIdx.x * 32 + (t & 31);     // grid.x = NU2/32
    int k = blockIdx.y * 8 + (t >> 5);      // grid.y = KTOT/8
    if (n >= d_Upad) return;
    int s = d_uniqPos[n];
    int ci = k / 9;
    int r  = k - ci * 9;
    int ky = r / 3;
    int kx = r - ky * 3;
    int y  = (s >> 7) + ky - 1;
    int xx = (s & 127) + kx - 1;
    float v = 0.0f;
    if (((unsigned)y < 128u) && ((unsigned)xx < 128u))
        v = x[ci * HW + y * GW + xx];
    d_Bg[k * NU2 + n] = v;
}

// ---------------- GEMM: partials, FFMA2, pipelined 64x64 tile / 64 thr / 8x8 regs ----------------
__global__ __launch_bounds__(64)
void gemm_kernel(const float* __restrict__ W) {
    int n0 = blockIdx.x * 64;
    if (n0 >= d_Upad) return;               // dedup early-exit (graph-safe, data-driven)
    __shared__ float2 As2[16][64];          // A duplicated pairs {v,v}, [k][m]
    __shared__ float  Bs[16][64];           // [k][n]
    int tid = threadIdx.x;
    int tx = tid & 7, ty = tid >> 3;
    int m0 = blockIdx.y * 64;
    int ks = blockIdx.z;
    int kbase = ks * KCH;

    const float* Ap = W + (m0 + tid) * KTOT + kbase;
    int bk = tid >> 2;
    int bn = (tid & 3) * 16;
    const float* Bp = d_Bg + (kbase + bk) * NU2 + n0 + bn;

    unsigned long long acc[8][4];
    #pragma unroll
    for (int i = 0; i < 8; i++)
        #pragma unroll
        for (int j = 0; j < 4; j++) acc[i][j] = 0ULL;

    // prologue load
    float4 a0 = *(const float4*)(Ap);
    float4 a1 = *(const float4*)(Ap + 4);
    float4 a2 = *(const float4*)(Ap + 8);
    float4 a3 = *(const float4*)(Ap + 12);
    float4 b0 = *(const float4*)(Bp);
    float4 b1 = *(const float4*)(Bp + 4);
    float4 b2 = *(const float4*)(Bp + 8);
    float4 b3 = *(const float4*)(Bp + 12);

    for (int k0 = 0; k0 < KCH; k0 += 16) {
        __syncthreads();
        {
            float va[16] = {a0.x, a0.y, a0.z, a0.w, a1.x, a1.y, a1.z, a1.w,
                            a2.x, a2.y, a2.z, a2.w, a3.x, a3.y, a3.z, a3.w};
            #pragma unroll
            for (int j = 0; j < 16; j++) As2[j][tid] = make_float2(va[j], va[j]);
        }
        *(float4*)&Bs[bk][bn]      = b0;
        *(float4*)&Bs[bk][bn + 4]  = b1;
        *(float4*)&Bs[bk][bn + 8]  = b2;
        *(float4*)&Bs[bk][bn + 12] = b3;
        __syncthreads();
        // prefetch next chunk while computing this one
        if (k0 + 16 < KCH) {
            const float* ap = Ap + k0 + 16;
            const float* bp = Bp + (k0 + 16) * NU2;
            a0 = *(const float4*)(ap);
            a1 = *(const float4*)(ap + 4);
            a2 = *(const float4*)(ap + 8);
            a3 = *(const float4*)(ap + 12);
            b0 = *(const float4*)(bp);
            b1 = *(const float4*)(bp + 4);
            b2 = *(const float4*)(bp + 8);
            b3 = *(const float4*)(bp + 12);
        }
        #pragma unroll
        for (int kk = 0; kk < 16; kk++) {
            const ulonglong2* ar = (const ulonglong2*)(&As2[kk][ty * 8]);
            ulonglong2 A0 = ar[0], A1 = ar[1], A2 = ar[2], A3 = ar[3];
            const ulonglong2* br = (const ulonglong2*)(&Bs[kk][tx * 8]);
            ulonglong2 B0 = br[0], B1 = br[1];
            unsigned long long am[8] = {A0.x, A0.y, A1.x, A1.y,
                                        A2.x, A2.y, A3.x, A3.y};
            unsigned long long bv[4] = {B0.x, B0.y, B1.x, B1.y};
            #pragma unroll
            for (int mi = 0; mi < 8; mi++)
                #pragma unroll
                for (int nj = 0; nj < 4; nj++)
                    acc[mi][nj] = ffma2(am[mi], bv[nj], acc[mi][nj]);
        }
    }
    // transposed partial store: d_hp[ks][u][m]
    #pragma unroll
    for (int j = 0; j < 8; j++) {
        float v[8];
        #pragma unroll
        for (int mi = 0; mi < 8; mi++) {
            float2 pr = *(float2*)&acc[mi][j >> 1];
            v[mi] = (j & 1) ? pr.y : pr.x;
        }
        float4* o = (float4*)(d_hp + (ks * NU2 + n0 + tx * 8 + j) * CIN + m0 + ty * 8);
        o[0] = make_float4(v[0], v[1], v[2], v[3]);
        o[1] = make_float4(v[4], v[5], v[6], v[7]);
    }
}

// ---------------- per-column 1x1 conv dot (fused partial-reduce + bias + relu) ----------------
__global__ void coldot_kernel(const float* __restrict__ bw, const float* __restrict__ bb,
                              const float* __restrict__ sw, const float* __restrict__ sb,
                              const float* __restrict__ conv_b) {
    int col = blockIdx.x * 8 + (threadIdx.x >> 5);
    int lane = threadIdx.x & 31;
    int npos = d_nPos;
    int u;
    if (col < 512)      { int t = col >> 2;         u = (t < npos) ? 1 + col : 0; }
    else if (col < 768) { int t = (col - 512) >> 1; u = (t < npos) ? 1 + 4 * npos + (col - 512) : 0; }
    else                { int g = (col - 768) >> 1; u = (g < 256 - npos) ? 1 + 6 * npos + (col - 768) : 0; }
    if (u == 0) return;   // invalid column: never read by the loss
    int meta = d_colMeta[col];
    const float* w;
    float b;
    if (meta < 36) { w = bw + meta * 512; b = bb[meta]; }
    else           { w = sw + (meta - 36) * 512; b = sb[meta - 36]; }
    const float4* wv = (const float4*)w;
    const float4* bias4 = (const float4*)conv_b;
    float s = 0.0f;
    for (int i = lane; i < 128; i += 32) {
        float4 a = bias4[i];
        #pragma unroll
        for (int ks = 0; ks < KSPLIT; ks++) {
            const float4* hp4 = (const float4*)(d_hp + (ks * NU2 + u) * CIN);
            float4 hv = hp4[i];
            a.x += hv.x; a.y += hv.y; a.z += hv.z; a.w += hv.w;
        }
        a.x = fmaxf(a.x, 0.0f); a.y = fmaxf(a.y, 0.0f);
        a.z = fmaxf(a.z, 0.0f); a.w = fmaxf(a.w, 0.0f);
        float4 ww = wv[i];
        s += a.x * ww.x + a.y * ww.y + a.z * ww.z + a.w * ww.w;
    }
    #pragma unroll
    for (int o = 16; o > 0; o >>= 1) s += __shfl_xor_sync(0xFFFFFFFFu, s, o);
    if (lane == 0) d_val[col] = fmaxf(s + b, 0.0f);
}

// ---------------- loss ----------------
__global__ void loss_kernel(const float* __restrict__ target, float* __restrict__ out) {
    __shared__ float rce[256], rsl[256], rvc[256];
    int t = threadIdx.x;
    float ce = 0.0f, sl = 0.0f, vc = 0.0f;
    if (t < 128 && d_posValid[t]) {
        float s0 = d_val[512 + 2 * t], s1 = d_val[512 + 2 * t + 1];
        float m = fmaxf(s0, s1);
        float lse = m + logf(expf(s0 - m) + expf(s1 - m));
        ce += lse - s0;
        vc += 1.0f;
        int p = d_posIdx[t];
        int k = p % 9;
        int q = p / 9;
        int wq = q & 127;
        int hq = q >> 7;
        float ax1 = hq * STEP, ay1 = wq * STEP;
        float aw = d_whw[k], ah = d_whh[k];
        float acx = ax1 + aw * 0.5f, acy = ay1 + ah * 0.5f;
        float4 tb = ((const float4*)target)[d_tgtIdx[p]];
        float bw_ = tb.z - tb.x, bh_ = tb.w - tb.y;
        float bcx = tb.x + bw_ * 0.5f, bcy = tb.y + bh_ * 0.5f;
        float tr[4] = {(bcx - acx) / aw, (bcy - acy) / ah,
                       logf(bw_ / aw), logf(bh_ / ah)};
        #pragma unroll
        for (int e = 0; e < 4; e++) {
            float d = d_val[4 * t + e] - tr[e];
            float ad = fabsf(d);
            sl += (ad < 1.0f) ? 0.5f * d * d : (ad - 0.5f);
        }
    }
    if (t < 256 && d_negValid[t]) {
        float s0 = d_val[768 + 2 * t], s1 = d_val[768 + 2 * t + 1];
        float m = fmaxf(s0, s1);
        float lse = m + logf(expf(s0 - m) + expf(s1 - m));
        ce += lse - s1;
        vc += 1.0f;
    }
    rce[t] = ce; rsl[t] = sl; rvc[t] = vc;
    __syncthreads();
    for (int s2 = 128; s2 > 0; s2 >>= 1) {
        if (t < s2) { rce[t] += rce[t + s2]; rsl[t] += rsl[t + s2]; rvc[t] += rvc[t + s2]; }
        __syncthreads();
    }
    if (t == 0) {
        float np = (float)d_nPos;
        float score_loss = rce[0] / fmaxf(rvc[0], 1.0f);
        float reg_loss = rsl[0] / fmaxf(np * 4.0f, 1.0f);
        out[0] = score_loss + 10.0f * reg_loss;
    }
}

// ---------------- launch ----------------
extern "C" void kernel_launch(void* const* d_in, const int* in_sizes, int n_in,
                              void* d_out, int out_size) {
    const float* x       = (const float*)d_in[0];
    const float* target  = (const float*)d_in[1];
    const float* conv_w  = (const float*)d_in[2];
    const float* conv_b  = (const float*)d_in[3];
    const float* bbox_w  = (const float*)d_in[4];
    const float* bbox_b  = (const float*)d_in[5];
    const float* score_w = (const float*)d_in[6];
    const float* score_b = (const float*)d_in[7];
    float* out = (float*)d_out;

    iou_kernel<<<NBLK, 256>>>(target);
    selection_kernel<<<1, 1024>>>();
    gather_kernel<<<dim3(NU2 / 32, KTOT / 8), 256>>>(x);
    gemm_kernel<<<dim3(NU2 / 64, CIN / 64, KSPLIT), 64>>>(conv_w);
    coldot_kernel<<<NCOL / 8, 256>>>(bbox_w, bbox_b, score_w, score_b, conv_b);
    loss_kernel<<<1, 256>>>(target, out);
}